// round 14
// baseline (speedup 1.0000x reference)
#include <cuda_runtime.h>
#include <cuda_fp16.h>
#include <mma.h>

using namespace nvcuda;

// GraphSAGENet: 50000 nodes, 800000 edges, feats 96 -> 48 -> 48 -> 48 -> 1
constexpr int NN = 50000;          // divisible by 16 (3125 wmma row-tiles)
constexpr int NE = 800000;
constexpr int F0 = 96;
constexpr int H  = 48;
constexpr int MO = 96;             // GEMM output width: [W_neigh | W_self]
constexpr int SLOT = 128;          // fixed per-node CSR slot
constexpr int SLD  = 20;           // padded per-warp stage leading dim (floats)

constexpr int XCAST_B = (NN * F0 / 4 + 255) / 256;   // 4688 (float4 units)
constexpr int WPREP_N = F0 * MO + 2 * H * MO;        // 18432
constexpr int WPREP_B = WPREP_N / 256;               // 72
constexpr int FILL_B  = NE / 256;                    // 3125 (256-thread blocks)
constexpr int NTILES  = (NN / 16) * 6;               // 18750 (row,n)-tile pairs
constexpr int GEMM_B  = (NTILES + 7) / 8;            // 2344 (8 warps/block)
constexpr int GQUAD   = (NN * 4 + 255) / 256;        // 782 (4 lanes per node)

// ---------------------------------------------------------------------------
// Static device scratch (g_cnt re-zeroed at tail of last kernel each call)
// ---------------------------------------------------------------------------
__device__ uint4 g_x16[NN * 12];   // fp16 x: 96 halfs = 192 B = 12 uint4 per row
__device__ uint4 g_zn [NN * 6];    // fp16 neighbor-transform rows (48 halfs)
__device__ float g_zs [NN * H];    // fp32 self-transform rows
__device__ uint4 g_h0 [NN * 6];    // fp16 h rows
__device__ uint4 g_h1 [NN * 6];
__device__ __align__(16) __half g_Wc0[F0 * MO];  // [Wn0 | Ws0] fp16
__device__ __align__(16) __half g_Wc1[H * MO];   // [Wn1 | Ws1]
__device__ __align__(16) __half g_Wc2[H * MO];   // [Wn2 | Ws2]
__device__ int   g_cnt[NN];        // per-node edge count (must be 0 on entry)
__device__ int   g_col[NN * SLOT]; // slotted CSR columns

// fp16 helpers
__device__ __forceinline__ float2 up2(unsigned u) {
    __half2 h = *reinterpret_cast<__half2*>(&u);
    return __half22float2(h);
}
__device__ __forceinline__ unsigned pack2(float a, float b) {
    __half2 h = __float22half2_rn(make_float2(a, b));
    return *reinterpret_cast<unsigned*>(&h);
}
__device__ __forceinline__ void acc_row(float* acc, uint4 a, uint2 b) {
    float2 f;
    f = up2(a.x); acc[0] += f.x; acc[1]  += f.y;
    f = up2(a.y); acc[2] += f.x; acc[3]  += f.y;
    f = up2(a.z); acc[4] += f.x; acc[5]  += f.y;
    f = up2(a.w); acc[6] += f.x; acc[7]  += f.y;
    f = up2(b.x); acc[8] += f.x; acc[9]  += f.y;
    f = up2(b.y); acc[10] += f.x; acc[11] += f.y;
}
// Feature mapping (4 lanes/node): lane t owns feats [8t..8t+7] (slots 0..7)
// and [32+4t..32+4t+3] (slots 8..11). fp16 row = 6 uint4.
__device__ __forceinline__ void store_h16(uint4* __restrict__ hrow, int t,
                                          const float* acc) {
    uint4 o;
    o.x = pack2(acc[0], acc[1]); o.y = pack2(acc[2], acc[3]);
    o.z = pack2(acc[4], acc[5]); o.w = pack2(acc[6], acc[7]);
    hrow[t] = o;
    reinterpret_cast<uint2*>(hrow + 4)[t] =
        make_uint2(pack2(acc[8], acc[9]), pack2(acc[10], acc[11]));
}
__device__ __forceinline__ void load_f32(const float* __restrict__ srcrow, int t,
                                         float* v) {
    const float4* s4 = reinterpret_cast<const float4*>(srcrow);
    float4 v0 = s4[2 * t];
    float4 v1 = s4[2 * t + 1];
    float4 v2 = reinterpret_cast<const float4*>(srcrow + 32)[t];
    v[0] = v0.x; v[1] = v0.y; v[2]  = v0.z; v[3]  = v0.w;
    v[4] = v1.x; v[5] = v1.y; v[6]  = v1.z; v[7]  = v1.w;
    v[8] = v2.x; v[9] = v2.y; v[10] = v2.z; v[11] = v2.w;
}

// ---------------------------------------------------------------------------
// Prep: x -> fp16 cast, weight concat+cast.
// ---------------------------------------------------------------------------
__global__ void k_prep(const float* __restrict__ x,
                       const float* __restrict__ wn0, const float* __restrict__ ws0,
                       const float* __restrict__ wn1, const float* __restrict__ ws1,
                       const float* __restrict__ wn2, const float* __restrict__ ws2) {
    int b = blockIdx.x;
    if (b < XCAST_B) {
        int i = b * 256 + threadIdx.x;            // float4 index
        if (i < NN * F0 / 4) {
            float4 v = reinterpret_cast<const float4*>(x)[i];
            __half2* o = reinterpret_cast<__half2*>(g_x16);
            o[2 * i]     = __float22half2_rn(make_float2(v.x, v.y));
            o[2 * i + 1] = __float22half2_rn(make_float2(v.z, v.w));
        }
        return;
    }
    b -= XCAST_B;
    int i = b * 256 + threadIdx.x;
    if (i < F0 * MO) {
        int k = i / MO, j = i % MO;
        g_Wc0[i] = __float2half(j < H ? wn0[k * H + j] : ws0[k * H + j - H]);
    } else if (i < F0 * MO + H * MO) {
        int ii = i - F0 * MO;
        int k = ii / MO, j = ii % MO;
        g_Wc1[ii] = __float2half(j < H ? wn1[k * H + j] : ws1[k * H + j - H]);
    } else if (i < WPREP_N) {
        int ii = i - F0 * MO - H * MO;
        int k = ii / MO, j = ii % MO;
        g_Wc2[ii] = __float2half(j < H ? wn2[k * H + j] : ws2[k * H + j - H]);
    }
}

// ---------------------------------------------------------------------------
// wmma GEMM body, N-split tiling: one warp = one (rowTile, nTile) 16x16
// output tile. 18750 warps total (~126/SM) -> latency fully hideable.
//   Z[N,96] = X16[N,KIN] @ Wc[KIN,96]  (fp16 x fp16 -> fp32)
// nTile 0..2 -> zn (fp16, gather layout); nTile 3..5 -> zs (fp32).
// ---------------------------------------------------------------------------
template <int KIN>
__device__ __forceinline__ void wgemm_body(int gb,
                                           const __half* __restrict__ X,
                                           const __half* __restrict__ Wc,
                                           __half* __restrict__ zn,
                                           float* __restrict__ zs) {
    __shared__ __align__(16) __half sW[KIN * MO];
    __shared__ __align__(16) float stage[8][16 * SLD];

    for (int i = threadIdx.x; i < KIN * MO / 8; i += 256)
        reinterpret_cast<uint4*>(sW)[i] = reinterpret_cast<const uint4*>(Wc)[i];
    __syncthreads();

    int warp = threadIdx.x >> 5;
    int lane = threadIdx.x & 31;
    int wgid = gb * 8 + warp;
    if (wgid >= NTILES) return;
    int rowBase = (wgid / 6) * 16;
    int nT = wgid % 6;

    // prefetch ALL A fragments (3 or 6 independent global loads)
    wmma::fragment<wmma::matrix_a, 16, 16, 16, __half, wmma::row_major> af[KIN / 16];
#pragma unroll
    for (int k = 0; k < KIN / 16; k++)
        wmma::load_matrix_sync(af[k], X + (size_t)rowBase * KIN + k * 16, KIN);

    wmma::fragment<wmma::accumulator, 16, 16, 16, float> acc;
    wmma::fill_fragment(acc, 0.0f);
#pragma unroll
    for (int k = 0; k < KIN / 16; k++) {
        wmma::fragment<wmma::matrix_b, 16, 16, 16, __half, wmma::row_major> bf;
        wmma::load_matrix_sync(bf, sW + (k * 16) * MO + nT * 16, MO);
        wmma::mma_sync(acc, af[k], bf, acc);
    }

    if (nT >= 3) {
        // zs fp32 direct
        wmma::store_matrix_sync(zs + (size_t)rowBase * H + (nT - 3) * 16, acc,
                                H, wmma::mem_row_major);
    } else {
        // zn fp16: padded stage + conversion sweep
        wmma::store_matrix_sync(stage[warp], acc, SLD, wmma::mem_row_major);
        __syncwarp();
        int r = lane >> 1;
        int c0 = (lane & 1) * 8;
        const float* sp = &stage[warp][r * SLD + c0];
        __half* op = zn + (size_t)(rowBase + r) * H + nT * 16 + c0;
#pragma unroll
        for (int q = 0; q < 4; q++)
            *reinterpret_cast<__half2*>(op + 2 * q) =
                __float22half2_rn(make_float2(sp[2 * q], sp[2 * q + 1]));
    }
}

// Fused launch: blocks [0,FILL_B) do slotted CSR fill; rest run GEMM-A.
__global__ void k_fill_wgemm(const int* __restrict__ src,
                             const int* __restrict__ dst) {
    if (blockIdx.x < FILL_B) {
        int e = blockIdx.x * 256 + threadIdx.x;
        int d = dst[e];
        int pos = atomicAdd(&g_cnt[d], 1);
        if (pos < SLOT) g_col[d * SLOT + pos] = src[e];
        return;
    }
    wgemm_body<F0>(blockIdx.x - FILL_B,
                   reinterpret_cast<const __half*>(g_x16), g_Wc0,
                   reinterpret_cast<__half*>(g_zn), g_zs);
}

// Standalone GEMM for layers 1/2: z = h @ Wc (KIN = 48)
__global__ void k_wgemm48(const uint4* __restrict__ hin,
                          const __half* __restrict__ Wc) {
    wgemm_body<H>(blockIdx.x, reinterpret_cast<const __half*>(hin), Wc,
                  reinterpret_cast<__half*>(g_zn), g_zs);
}

// ---------------------------------------------------------------------------
// Gather + combine (1 node per 4 lanes — proven shape, unchanged):
//   agg = sum_{s in N(n)} zn[s]   (slot segment [n*SLOT, n*SLOT+cnt[n]) )
//   h   = relu(zs[n] + b + agg / max(deg,1))
//   !PRED: store h (fp16) ; PRED: out[n] = h . wpred + bpred (+ cnt reset)
// ---------------------------------------------------------------------------
template <bool PRED>
__global__ void k_gather_combine(const float* __restrict__ bias,
                                 const float* __restrict__ wp,
                                 const float* __restrict__ bp,
                                 uint4* __restrict__ hout,
                                 float* __restrict__ outp) {
    __shared__ float sb[H];
    __shared__ float sWp[H];
    if (threadIdx.x < H) {
        sb[threadIdx.x] = bias[threadIdx.x];
        if constexpr (PRED) sWp[threadIdx.x] = wp[threadIdx.x];
    }
    __syncthreads();

    int gid = blockIdx.x * 256 + threadIdx.x;
    int n = gid >> 2;
    int t = gid & 3;
    if (n >= NN) return;   // warp-aligned (NN*4 % 32 == 0)

    const uint4* yin = g_zn;
    float acc[12];
#pragma unroll
    for (int j = 0; j < 12; j++) acc[j] = 0.0f;

    int deg = g_cnt[n];
    int e = n * SLOT;
    int end = e + (deg < SLOT ? deg : SLOT);
    for (; e + 2 <= end; e += 2) {
        int s0 = g_col[e];
        int s1 = g_col[e + 1];
        const uint4* r0 = yin + (size_t)s0 * 6;
        const uint4* r1 = yin + (size_t)s1 * 6;
        uint4 a0 = r0[t];
        uint2 b0 = reinterpret_cast<const uint2*>(r0 + 4)[t];
        uint4 a1 = r1[t];
        uint2 b1 = reinterpret_cast<const uint2*>(r1 + 4)[t];
        acc_row(acc, a0, b0);
        acc_row(acc, a1, b1);
    }
    if (e < end) {
        int s0 = g_col[e];
        const uint4* r0 = yin + (size_t)s0 * 6;
        uint4 a0 = r0[t];
        uint2 b0 = reinterpret_cast<const uint2*>(r0 + 4)[t];
        acc_row(acc, a0, b0);
    }

    // combine: h = relu(zs + b + acc/deg)
    float di = 1.0f / (float)(deg > 1 ? deg : 1);
    float zsv[12];
    load_f32(g_zs + (size_t)n * H, t, zsv);
#pragma unroll
    for (int j = 0; j < 8; j++)
        acc[j] = fmaxf(zsv[j] + sb[t * 8 + j] + acc[j] * di, 0.0f);
#pragma unroll
    for (int j = 0; j < 4; j++)
        acc[8 + j] = fmaxf(zsv[8 + j] + sb[32 + t * 4 + j] + acc[8 + j] * di, 0.0f);

    if constexpr (!PRED) {
        store_h16(hout + (size_t)n * 6, t, acc);
    } else {
        float p = 0.0f;
#pragma unroll
        for (int j = 0; j < 8; j++) p += acc[j] * sWp[t * 8 + j];
#pragma unroll
        for (int j = 0; j < 4; j++) p += acc[8 + j] * sWp[32 + t * 4 + j];
        p += __shfl_down_sync(0xffffffffu, p, 1);
        p += __shfl_down_sync(0xffffffffu, p, 2);
        if (t == 0) outp[n] = p + bp[0];
        if (t == 0) g_cnt[n] = 0;   // state reset for next call
    }
}

// ---------------------------------------------------------------------------
extern "C" void kernel_launch(void* const* d_in, const int* in_sizes, int n_in,
                              void* d_out, int out_size) {
    const float* x        = (const float*)d_in[0];
    const int*   edge     = (const int*)d_in[1];
    const float* w_self0  = (const float*)d_in[2];
    const float* w_neigh0 = (const float*)d_in[3];
    const float* b0       = (const float*)d_in[4];
    const float* w_self1  = (const float*)d_in[5];
    const float* w_neigh1 = (const float*)d_in[6];
    const float* b1       = (const float*)d_in[7];
    const float* w_self2  = (const float*)d_in[8];
    const float* w_neigh2 = (const float*)d_in[9];
    const float* b2       = (const float*)d_in[10];
    const float* w_pred   = (const float*)d_in[11];
    const float* b_pred   = (const float*)d_in[12];
    float* out = (float*)d_out;

    const int* src = edge;
    const int* dst = edge + NE;

    uint4 *h0, *h1;
    cudaGetSymbolAddress((void**)&h0, g_h0);
    cudaGetSymbolAddress((void**)&h1, g_h1);

    const __half *Wc1p, *Wc2p;
    cudaGetSymbolAddress((void**)&Wc1p, g_Wc1);
    cudaGetSymbolAddress((void**)&Wc2p, g_Wc2);

    // 1. prep: x cast + weight concat
    k_prep<<<XCAST_B + WPREP_B, 256>>>(
        x, w_neigh0, w_self0, w_neigh1, w_self1, w_neigh2, w_self2);
    // 2. slotted CSR fill (parallel with) GEMM-A: z0 = x16 @ [Wn0|Ws0]
    k_fill_wgemm<<<FILL_B + GEMM_B, 256>>>(src, dst);

    // 3. Layer 0: h0 = relu(zs0 + b0 + agg(zn0)/deg)
    k_gather_combine<false><<<GQUAD, 256>>>(b0, nullptr, nullptr, h0, nullptr);
    // 4. GEMM-B: z1 = h0 @ [Wn1|Ws1]
    k_wgemm48<<<GEMM_B, 256>>>(h0, Wc1p);
    // 5. Layer 1
    k_gather_combine<false><<<GQUAD, 256>>>(b1, nullptr, nullptr, h1, nullptr);
    // 6. GEMM-C: z2 = h1 @ [Wn2|Ws2]
    k_wgemm48<<<GEMM_B, 256>>>(h1, Wc2p);
    // 7. Layer 2 + head (+ cnt reset for next call)
    k_gather_combine<true><<<GQUAD, 256>>>(b2, w_pred, b_pred, nullptr, out);
}

// round 15
// speedup vs baseline: 1.1336x; 1.1336x over previous
#include <cuda_runtime.h>
#include <cuda_fp16.h>
#include <mma.h>

using namespace nvcuda;

// GraphSAGENet: 50000 nodes, 800000 edges, feats 96 -> 48 -> 48 -> 48 -> 1
constexpr int NN = 50000;          // divisible by 16 (3125 wmma row-tiles)
constexpr int NE = 800000;
constexpr int F0 = 96;
constexpr int H  = 48;
constexpr int MO = 96;             // GEMM output width: [W_neigh | W_self]
constexpr int SLOT = 128;          // fixed per-node CSR slot
constexpr int SLD  = 52;           // padded stage leading dim (floats)

constexpr int XCAST_B = (NN * F0 / 4 + 255) / 256;   // 4688 (float4 units)
constexpr int WPREP_N = F0 * MO + 2 * H * MO;        // 18432
constexpr int WPREP_B = WPREP_N / 256;               // 72
constexpr int FILL_B  = NE / 256;                    // 3125 (256-thread blocks)
constexpr int NWTILE  = (NN / 16) * 2;               // 6250 (row-tile, half) pairs
constexpr int GEMM_B  = (NWTILE + 7) / 8;            // 782 (8 warps/block)
constexpr int GQUAD   = (NN * 4 + 255) / 256;        // 782 (4 lanes per node)

// ---------------------------------------------------------------------------
// Static device scratch (g_cnt re-zeroed at tail of last kernel each call)
// ---------------------------------------------------------------------------
__device__ uint4 g_x16[NN * 12];   // fp16 x: 96 halfs = 192 B = 12 uint4 per row
__device__ uint4 g_zn [NN * 6];    // fp16 neighbor-transform rows (48 halfs)
__device__ float g_zs [NN * H];    // fp32 self-transform rows
__device__ uint4 g_h0 [NN * 6];    // fp16 h rows
__device__ uint4 g_h1 [NN * 6];
__device__ __align__(16) __half g_Wc0[F0 * MO];  // [Wn0 | Ws0] fp16
__device__ __align__(16) __half g_Wc1[H * MO];   // [Wn1 | Ws1]
__device__ __align__(16) __half g_Wc2[H * MO];   // [Wn2 | Ws2]
__device__ int   g_cnt[NN];        // per-node edge count (must be 0 on entry)
__device__ int   g_col[NN * SLOT]; // slotted CSR columns

// fp16 helpers
__device__ __forceinline__ float2 up2(unsigned u) {
    __half2 h = *reinterpret_cast<__half2*>(&u);
    return __half22float2(h);
}
__device__ __forceinline__ unsigned pack2(float a, float b) {
    __half2 h = __float22half2_rn(make_float2(a, b));
    return *reinterpret_cast<unsigned*>(&h);
}
__device__ __forceinline__ void acc_row(float* acc, uint4 a, uint2 b) {
    float2 f;
    f = up2(a.x); acc[0] += f.x; acc[1]  += f.y;
    f = up2(a.y); acc[2] += f.x; acc[3]  += f.y;
    f = up2(a.z); acc[4] += f.x; acc[5]  += f.y;
    f = up2(a.w); acc[6] += f.x; acc[7]  += f.y;
    f = up2(b.x); acc[8] += f.x; acc[9]  += f.y;
    f = up2(b.y); acc[10] += f.x; acc[11] += f.y;
}
// Feature mapping (4 lanes/node): lane t owns feats [8t..8t+7] (slots 0..7)
// and [32+4t..32+4t+3] (slots 8..11). fp16 row = 6 uint4.
__device__ __forceinline__ void store_h16(uint4* __restrict__ hrow, int t,
                                          const float* acc) {
    uint4 o;
    o.x = pack2(acc[0], acc[1]); o.y = pack2(acc[2], acc[3]);
    o.z = pack2(acc[4], acc[5]); o.w = pack2(acc[6], acc[7]);
    hrow[t] = o;
    reinterpret_cast<uint2*>(hrow + 4)[t] =
        make_uint2(pack2(acc[8], acc[9]), pack2(acc[10], acc[11]));
}
__device__ __forceinline__ void load_f32(const float* __restrict__ srcrow, int t,
                                         float* v) {
    const float4* s4 = reinterpret_cast<const float4*>(srcrow);
    float4 v0 = s4[2 * t];
    float4 v1 = s4[2 * t + 1];
    float4 v2 = reinterpret_cast<const float4*>(srcrow + 32)[t];
    v[0] = v0.x; v[1] = v0.y; v[2]  = v0.z; v[3]  = v0.w;
    v[4] = v1.x; v[5] = v1.y; v[6]  = v1.z; v[7]  = v1.w;
    v[8] = v2.x; v[9] = v2.y; v[10] = v2.z; v[11] = v2.w;
}

// ---------------------------------------------------------------------------
// Prep: x -> fp16 cast, weight concat+cast.
// ---------------------------------------------------------------------------
__global__ void k_prep(const float* __restrict__ x,
                       const float* __restrict__ wn0, const float* __restrict__ ws0,
                       const float* __restrict__ wn1, const float* __restrict__ ws1,
                       const float* __restrict__ wn2, const float* __restrict__ ws2) {
    int b = blockIdx.x;
    if (b < XCAST_B) {
        int i = b * 256 + threadIdx.x;            // float4 index
        if (i < NN * F0 / 4) {
            float4 v = reinterpret_cast<const float4*>(x)[i];
            __half2* o = reinterpret_cast<__half2*>(g_x16);
            o[2 * i]     = __float22half2_rn(make_float2(v.x, v.y));
            o[2 * i + 1] = __float22half2_rn(make_float2(v.z, v.w));
        }
        return;
    }
    b -= XCAST_B;
    int i = b * 256 + threadIdx.x;
    if (i < F0 * MO) {
        int k = i / MO, j = i % MO;
        g_Wc0[i] = __float2half(j < H ? wn0[k * H + j] : ws0[k * H + j - H]);
    } else if (i < F0 * MO + H * MO) {
        int ii = i - F0 * MO;
        int k = ii / MO, j = ii % MO;
        g_Wc1[ii] = __float2half(j < H ? wn1[k * H + j] : ws1[k * H + j - H]);
    } else if (i < WPREP_N) {
        int ii = i - F0 * MO - H * MO;
        int k = ii / MO, j = ii % MO;
        g_Wc2[ii] = __float2half(j < H ? wn2[k * H + j] : ws2[k * H + j - H]);
    }
}

// ---------------------------------------------------------------------------
// wmma GEMM body, 2-way N-split: one warp = one (rowTile, half) pair.
//   half 0 -> zn cols 0..47 (fp16, gather layout, staged epilogue)
//   half 1 -> zs cols 48..95 (fp32 direct store)
// 6250 warps (~42/SM). A fragments read 2x chip-wide (L2-resident, cheap).
//   Z[N,96] = X16[N,KIN] @ Wc[KIN,96]  (fp16 x fp16 -> fp32)
// ---------------------------------------------------------------------------
template <int KIN>
__device__ __forceinline__ void wgemm_body(int gb,
                                           const __half* __restrict__ X,
                                           const __half* __restrict__ Wc,
                                           __half* __restrict__ zn,
                                           float* __restrict__ zs) {
    __shared__ __align__(16) __half sW[KIN * MO];
    __shared__ __align__(16) float stage[4][16 * SLD];  // half-0 warps only

    for (int i = threadIdx.x; i < KIN * MO / 8; i += 256)
        reinterpret_cast<uint4*>(sW)[i] = reinterpret_cast<const uint4*>(Wc)[i];
    __syncthreads();

    int warp = threadIdx.x >> 5;
    int lane = threadIdx.x & 31;
    int wgid = gb * 8 + warp;
    if (wgid >= NWTILE) return;
    int rowBase = (wgid >> 1) * 16;
    int half = wgid & 1;
    int colBase = half * 48;

    wmma::fragment<wmma::accumulator, 16, 16, 16, float> acc[3];
#pragma unroll
    for (int n = 0; n < 3; n++) wmma::fill_fragment(acc[n], 0.0f);

#pragma unroll
    for (int kh = 0; kh < KIN / 48; kh++) {
        // prefetch 3 A fragments (independent global loads -> MLP 3)
        wmma::fragment<wmma::matrix_a, 16, 16, 16, __half, wmma::row_major> af[3];
#pragma unroll
        for (int kk = 0; kk < 3; kk++)
            wmma::load_matrix_sync(af[kk],
                X + (size_t)rowBase * KIN + kh * 48 + kk * 16, KIN);
#pragma unroll
        for (int kk = 0; kk < 3; kk++) {
            int k = kh * 48 + kk * 16;
#pragma unroll
            for (int n = 0; n < 3; n++) {
                wmma::fragment<wmma::matrix_b, 16, 16, 16, __half, wmma::row_major> bf;
                wmma::load_matrix_sync(bf, sW + k * MO + colBase + n * 16, MO);
                wmma::mma_sync(acc[n], af[kk], bf, acc[n]);
            }
        }
    }

    if (half) {
        // zs fp32 direct
#pragma unroll
        for (int n = 0; n < 3; n++)
            wmma::store_matrix_sync(zs + (size_t)rowBase * H + n * 16, acc[n],
                                    H, wmma::mem_row_major);
    } else {
        // zn fp16: one padded stage pass, one syncwarp
        float* st = stage[warp >> 1];
#pragma unroll
        for (int n = 0; n < 3; n++)
            wmma::store_matrix_sync(&st[n * 16], acc[n], SLD, wmma::mem_row_major);
        __syncwarp();
        int r = lane >> 1;
        int c0 = (lane & 1) * 24;
        const float* sp = &st[r * SLD + c0];
        __half* op = zn + (size_t)(rowBase + r) * H + c0;
#pragma unroll
        for (int q = 0; q < 12; q++)
            *reinterpret_cast<__half2*>(op + 2 * q) =
                __float22half2_rn(make_float2(sp[2 * q], sp[2 * q + 1]));
    }
}

// Fused launch: blocks [0,FILL_B) do slotted CSR fill; rest run GEMM-A.
__global__ void k_fill_wgemm(const int* __restrict__ src,
                             const int* __restrict__ dst) {
    if (blockIdx.x < FILL_B) {
        int e = blockIdx.x * 256 + threadIdx.x;
        int d = dst[e];
        int pos = atomicAdd(&g_cnt[d], 1);
        if (pos < SLOT) g_col[d * SLOT + pos] = src[e];
        return;
    }
    wgemm_body<F0>(blockIdx.x - FILL_B,
                   reinterpret_cast<const __half*>(g_x16), g_Wc0,
                   reinterpret_cast<__half*>(g_zn), g_zs);
}

// Standalone GEMM for layers 1/2: z = h @ Wc (KIN = 48)
__global__ void k_wgemm48(const uint4* __restrict__ hin,
                          const __half* __restrict__ Wc) {
    wgemm_body<H>(blockIdx.x, reinterpret_cast<const __half*>(hin), Wc,
                  reinterpret_cast<__half*>(g_zn), g_zs);
}

// ---------------------------------------------------------------------------
// Gather + combine (1 node per 4 lanes — proven shape, unchanged):
//   agg = sum_{s in N(n)} zn[s]   (slot segment [n*SLOT, n*SLOT+cnt[n]) )
//   h   = relu(zs[n] + b + agg / max(deg,1))
//   !PRED: store h (fp16) ; PRED: out[n] = h . wpred + bpred (+ cnt reset)
// ---------------------------------------------------------------------------
template <bool PRED>
__global__ void k_gather_combine(const float* __restrict__ bias,
                                 const float* __restrict__ wp,
                                 const float* __restrict__ bp,
                                 uint4* __restrict__ hout,
                                 float* __restrict__ outp) {
    __shared__ float sb[H];
    __shared__ float sWp[H];
    if (threadIdx.x < H) {
        sb[threadIdx.x] = bias[threadIdx.x];
        if constexpr (PRED) sWp[threadIdx.x] = wp[threadIdx.x];
    }
    __syncthreads();

    int gid = blockIdx.x * 256 + threadIdx.x;
    int n = gid >> 2;
    int t = gid & 3;
    if (n >= NN) return;   // warp-aligned (NN*4 % 32 == 0)

    const uint4* yin = g_zn;
    float acc[12];
#pragma unroll
    for (int j = 0; j < 12; j++) acc[j] = 0.0f;

    int deg = g_cnt[n];
    int e = n * SLOT;
    int end = e + (deg < SLOT ? deg : SLOT);
    for (; e + 2 <= end; e += 2) {
        int s0 = g_col[e];
        int s1 = g_col[e + 1];
        const uint4* r0 = yin + (size_t)s0 * 6;
        const uint4* r1 = yin + (size_t)s1 * 6;
        uint4 a0 = r0[t];
        uint2 b0 = reinterpret_cast<const uint2*>(r0 + 4)[t];
        uint4 a1 = r1[t];
        uint2 b1 = reinterpret_cast<const uint2*>(r1 + 4)[t];
        acc_row(acc, a0, b0);
        acc_row(acc, a1, b1);
    }
    if (e < end) {
        int s0 = g_col[e];
        const uint4* r0 = yin + (size_t)s0 * 6;
        uint4 a0 = r0[t];
        uint2 b0 = reinterpret_cast<const uint2*>(r0 + 4)[t];
        acc_row(acc, a0, b0);
    }

    // combine: h = relu(zs + b + acc/deg)
    float di = 1.0f / (float)(deg > 1 ? deg : 1);
    float zsv[12];
    load_f32(g_zs + (size_t)n * H, t, zsv);
#pragma unroll
    for (int j = 0; j < 8; j++)
        acc[j] = fmaxf(zsv[j] + sb[t * 8 + j] + acc[j] * di, 0.0f);
#pragma unroll
    for (int j = 0; j < 4; j++)
        acc[8 + j] = fmaxf(zsv[8 + j] + sb[32 + t * 4 + j] + acc[8 + j] * di, 0.0f);

    if constexpr (!PRED) {
        store_h16(hout + (size_t)n * 6, t, acc);
    } else {
        float p = 0.0f;
#pragma unroll
        for (int j = 0; j < 8; j++) p += acc[j] * sWp[t * 8 + j];
#pragma unroll
        for (int j = 0; j < 4; j++) p += acc[8 + j] * sWp[32 + t * 4 + j];
        p += __shfl_down_sync(0xffffffffu, p, 1);
        p += __shfl_down_sync(0xffffffffu, p, 2);
        if (t == 0) outp[n] = p + bp[0];
        if (t == 0) g_cnt[n] = 0;   // state reset for next call
    }
}

// ---------------------------------------------------------------------------
extern "C" void kernel_launch(void* const* d_in, const int* in_sizes, int n_in,
                              void* d_out, int out_size) {
    const float* x        = (const float*)d_in[0];
    const int*   edge     = (const int*)d_in[1];
    const float* w_self0  = (const float*)d_in[2];
    const float* w_neigh0 = (const float*)d_in[3];
    const float* b0       = (const float*)d_in[4];
    const float* w_self1  = (const float*)d_in[5];
    const float* w_neigh1 = (const float*)d_in[6];
    const float* b1       = (const float*)d_in[7];
    const float* w_self2  = (const float*)d_in[8];
    const float* w_neigh2 = (const float*)d_in[9];
    const float* b2       = (const float*)d_in[10];
    const float* w_pred   = (const float*)d_in[11];
    const float* b_pred   = (const float*)d_in[12];
    float* out = (float*)d_out;

    const int* src = edge;
    const int* dst = edge + NE;

    uint4 *h0, *h1;
    cudaGetSymbolAddress((void**)&h0, g_h0);
    cudaGetSymbolAddress((void**)&h1, g_h1);

    const __half *Wc1p, *Wc2p;
    cudaGetSymbolAddress((void**)&Wc1p, g_Wc1);
    cudaGetSymbolAddress((void**)&Wc2p, g_Wc2);

    // 1. prep: x cast + weight concat
    k_prep<<<XCAST_B + WPREP_B, 256>>>(
        x, w_neigh0, w_self0, w_neigh1, w_self1, w_neigh2, w_self2);
    // 2. slotted CSR fill (parallel with) GEMM-A: z0 = x16 @ [Wn0|Ws0]
    k_fill_wgemm<<<FILL_B + GEMM_B, 256>>>(src, dst);

    // 3. Layer 0: h0 = relu(zs0 + b0 + agg(zn0)/deg)
    k_gather_combine<false><<<GQUAD, 256>>>(b0, nullptr, nullptr, h0, nullptr);
    // 4. GEMM-B: z1 = h0 @ [Wn1|Ws1]
    k_wgemm48<<<GEMM_B, 256>>>(h0, Wc1p);
    // 5. Layer 1
    k_gather_combine<false><<<GQUAD, 256>>>(b1, nullptr, nullptr, h1, nullptr);
    // 6. GEMM-C: z2 = h1 @ [Wn2|Ws2]
    k_wgemm48<<<GEMM_B, 256>>>(h1, Wc2p);
    // 7. Layer 2 + head (+ cnt reset for next call)
    k_gather_combine<true><<<GQUAD, 256>>>(b2, w_pred, b_pred, nullptr, out);
}